// round 7
// baseline (speedup 1.0000x reference)
#include <cuda_runtime.h>

#define BATCH   2097152
#define DIMC    32
#define INDIM   10
#define LAYERS  4
#define MB      17
#define EPSV    1e-5f

#define GRID_MAIN 2048
#define TPB       256
#define SWEEPS    2            // 2048 CTAs * 256 thr * 2 rows * 2 sweeps = BATCH

typedef unsigned long long u64;

// ---------------- scratch (__device__ globals: allocation-free) ----------------
__device__ __align__(16) float g_h[(size_t)DIMC * BATCH];   // planar [c][row]
__device__ __align__(16) float g_r[(size_t)DIMC * BATCH];   // planar [c][row]
__device__ __align__(16) float g_A[LAYERS * DIMC * DIMC];   // fused Fourier A+I, [l][in][out]
__device__ float g_partials[GRID_MAIN * 64];                // per-CTA [sum[32], sumsq[32]]
__device__ float g_scale[DIMC];                             // BN affine: y = x*scale + shift
__device__ float g_shift[DIMC];

// ---------------- packed f32x2 helpers ----------------
__device__ __forceinline__ u64 pk2(float a, float b){
    u64 r; asm("mov.b64 %0,{%1,%2};" : "=l"(r) : "f"(a), "f"(b)); return r;
}
__device__ __forceinline__ void up2(u64 v, float &a, float &b){
    asm("mov.b64 {%0,%1},%2;" : "=f"(a), "=f"(b) : "l"(v));
}
__device__ __forceinline__ u64 fma2(u64 a, u64 b, u64 c){
    u64 d; asm("fma.rn.f32x2 %0,%1,%2,%3;" : "=l"(d) : "l"(a), "l"(b), "l"(c)); return d;
}
__device__ __forceinline__ float siluf(float x){
    return x * __fdividef(1.0f, 1.0f + __expf(-x));
}

// ------- Fourier operator precompute: A' = A + I. One thread per element. -------
__global__ void k_precompute_A(const float* __restrict__ wr, const float* __restrict__ wi){
    __shared__ double ct[32], st[32];
    int t = threadIdx.x;
    if(t < 32){
        double ang = 6.283185307179586476925286766559 * (double)t / 32.0;
        ct[t] = cos(ang); st[t] = sin(ang);
    }
    __syncthreads();
    int g = blockIdx.x * blockDim.x + t;               // 0..4095
    if(g >= LAYERS*DIMC*DIMC) return;
    int l = g >> 10, j = (g >> 5) & 31, d = g & 31;
    const float* WR = wr + l*MB*MB;
    const float* WI = wi + l*MB*MB;
    double v = 0.0;
    for(int k = 0; k < MB; k++){
        double re = 0.0, im = 0.0;
        for(int m = 0; m < MB; m++){
            double c = ct[(m*j)&31], s = st[(m*j)&31];   // rfft of e_j: c - i*s
            double a = (double)WR[m*MB + k], b = (double)WI[m*MB + k];
            re += c*a + s*b;
            im += c*b - s*a;
        }
        double al, be;
        if(k == 0)      { al = 1.0; be = 0.0; }
        else if(k == 16){ al = (d & 1) ? -1.0 : 1.0; be = 0.0; }
        else            { al = 2.0*ct[(k*d)&31]; be = 2.0*st[(k*d)&31]; }
        v += al*re - be*im;
    }
    v *= (1.0/32.0);
    if(j == d) v += 1.0;                                  // fold identity skip
    g_A[(l*DIMC + j)*DIMC + d] = (float)v;
}

// stats helpers: tile is float[8704], logical [256 rows][34], u64-friendly stride
#define STATS_PHASE(ACC) do{                                                   \
    __syncthreads();                                                           \
    { u64* trow = (u64*)(tile + threadIdx.x*34);                               \
      _Pragma("unroll")                                                        \
      for(int q = 0; q < 16; q++) trow[q] = (ACC)[q]; }                        \
    __syncthreads();                                                           \
    _Pragma("unroll")                                                          \
    for(int j = 0; j < 32; j++){                                               \
        float v = tile[(mrow*32 + j)*34 + ch];                                 \
        ssum += v; ssq += v*v;                                                 \
    }                                                                          \
}while(0)

#define STATS_TAIL() do{                                                       \
    __syncthreads();                                                           \
    tile[mrow*64 + ch]      = ssum;                                            \
    tile[mrow*64 + 32 + ch] = ssq;                                             \
    __syncthreads();                                                           \
    if(threadIdx.x < 64){                                                      \
        float v = 0.f;                                                         \
        _Pragma("unroll")                                                      \
        for(int m = 0; m < 8; m++) v += tile[m*64 + threadIdx.x];              \
        g_partials[blockIdx.x*64 + threadIdx.x] = v;                           \
    }                                                                          \
}while(0)

// one k-step of the paired GEMV: acc{A,B}[16] += sp{A,B} * w[k][:]
#define GEMV_STEP(WSH, K, SPA, SPB) do{                                        \
    const ulonglong2* _w2 = (const ulonglong2*)((WSH) + (K)*16);               \
    _Pragma("unroll")                                                          \
    for(int i = 0; i < 8; i++){                                                \
        ulonglong2 ww = _w2[i];                                                \
        accA[2*i]   = fma2((SPA), ww.x, accA[2*i]);                            \
        accB[2*i]   = fma2((SPB), ww.x, accB[2*i]);                            \
        accA[2*i+1] = fma2((SPA), ww.y, accA[2*i+1]);                          \
        accB[2*i+1] = fma2((SPB), ww.y, accB[2*i+1]);                          \
    }                                                                          \
}while(0)

// ---------------- stem: h = x@stem_w + b; stats(h) ----------------
__global__ __launch_bounds__(TPB, 3) void k_stem(const float* __restrict__ x,
                                                 const float* __restrict__ sw,
                                                 const float* __restrict__ sb){
    __shared__ __align__(16) u64 wsh[INDIM*16];
    __shared__ u64 bsh[16];
    __shared__ float tile[8704];
    if(threadIdx.x < INDIM*16){
        int r = threadIdx.x >> 4, q = threadIdx.x & 15;
        wsh[threadIdx.x] = pk2(sw[r*DIMC + 2*q], sw[r*DIMC + 2*q + 1]);
    }
    if(threadIdx.x < 16) bsh[threadIdx.x] = pk2(sb[2*threadIdx.x], sb[2*threadIdx.x+1]);
    int ch = threadIdx.x & 31, mrow = threadIdx.x >> 5;
    float ssum = 0.f, ssq = 0.f;
    __syncthreads();
#pragma unroll 1
    for(int s = 0; s < SWEEPS; ++s){
        int rowbase = blockIdx.x*1024 + s*512;
        int row0 = rowbase + 2*threadIdx.x;
        // stage x coalesced: 512 rows * 10 floats
        __syncthreads();
        for(int i = threadIdx.x; i < 512*INDIM; i += TPB)
            tile[i] = x[(size_t)rowbase*INDIM + i];
        __syncthreads();
        u64 accA[16], accB[16];
#pragma unroll
        for(int q = 0; q < 16; q++){ accA[q] = bsh[q]; accB[q] = bsh[q]; }
#pragma unroll
        for(int i = 0; i < INDIM; i++){
            float xa = tile[(2*threadIdx.x)*INDIM + i];
            float xb = tile[(2*threadIdx.x+1)*INDIM + i];
            u64 spA = pk2(xa, xa), spB = pk2(xb, xb);
            GEMV_STEP(wsh, i, spA, spB);
        }
        STATS_PHASE(accA);
        STATS_PHASE(accB);
#pragma unroll
        for(int q = 0; q < 16; q++){
            float a0,a1,b0,b1; up2(accA[q],a0,a1); up2(accB[q],b0,b1);
            *(u64*)(g_h + (size_t)(2*q)*BATCH + row0)   = pk2(a0,b0);
            *(u64*)(g_h + (size_t)(2*q+1)*BATCH + row0) = pk2(a1,b1);
        }
    }
    STATS_TAIL();
}

// ---------------- finalize: partials -> BN scale/shift ----------------
__global__ void k_fin(const float* __restrict__ gamma, const float* __restrict__ beta, int layer){
    __shared__ float red[1024];
    __shared__ float tot[64];
    int t = threadIdx.x;                 // 1024 threads
    int col = t & 63, part = t >> 6;     // 16 groups x 128 rows
    const float* p = g_partials + (size_t)part*128*64 + col;
    float v = 0.f;
#pragma unroll 8
    for(int i = 0; i < 128; i++) v += p[(size_t)i*64];
    red[part*64 + col] = v;
    __syncthreads();
    if(t < 64){
        float s = 0.f;
#pragma unroll
        for(int q = 0; q < 16; q++) s += red[q*64 + t];
        tot[t] = s;
    }
    __syncthreads();
    if(t < DIMC){
        float mean = tot[t]      * (1.0f/(float)BATCH);
        float ex2  = tot[32 + t] * (1.0f/(float)BATCH);
        float var  = fmaxf(ex2 - mean*mean, 0.0f);
        float sc   = gamma[layer*DIMC + t] * rsqrtf(var + EPSV);
        g_scale[t] = sc;
        g_shift[t] = beta[layer*DIMC + t] - mean*sc;
    }
}

// ---------------- pass A: r = silu(bn1(h))@lin1 + b1; stats(r) ----------------
__global__ __launch_bounds__(TPB, 3) void k_passA(const float* __restrict__ w1,
                                                  const float* __restrict__ b1, int layer){
    __shared__ __align__(16) u64 wsh[512];
    __shared__ u64 bsh[16];
    __shared__ float2 bn[DIMC];
    __shared__ float tile[8704];
    {
        const u64* src = (const u64*)(w1 + layer*DIMC*DIMC);
        for(int i = threadIdx.x; i < 512; i += TPB) wsh[i] = src[i];
    }
    if(threadIdx.x < DIMC) bn[threadIdx.x] = make_float2(g_scale[threadIdx.x], g_shift[threadIdx.x]);
    if(threadIdx.x < 16){
        const float* bb = b1 + layer*DIMC;
        bsh[threadIdx.x] = pk2(bb[2*threadIdx.x], bb[2*threadIdx.x+1]);
    }
    int ch = threadIdx.x & 31, mrow = threadIdx.x >> 5;
    float ssum = 0.f, ssq = 0.f;
    __syncthreads();
#pragma unroll 1
    for(int s = 0; s < SWEEPS; ++s){
        int row0 = blockIdx.x*1024 + s*512 + 2*threadIdx.x;
        u64 accA[16], accB[16];
#pragma unroll
        for(int q = 0; q < 16; q++){ accA[q] = bsh[q]; accB[q] = bsh[q]; }
#pragma unroll
        for(int k = 0; k < DIMC; k++){
            u64 hh = *(const u64*)(g_h + (size_t)k*BATCH + row0);
            float hA, hB; up2(hh, hA, hB);
            float2 p = bn[k];
            float sA = siluf(fmaf(hA, p.x, p.y));
            float sB = siluf(fmaf(hB, p.x, p.y));
            u64 spA = pk2(sA, sA), spB = pk2(sB, sB);
            GEMV_STEP(wsh, k, spA, spB);
        }
        STATS_PHASE(accA);
        STATS_PHASE(accB);
#pragma unroll
        for(int q = 0; q < 16; q++){
            float a0,a1,b0,b1; up2(accA[q],a0,a1); up2(accB[q],b0,b1);
            *(u64*)(g_r + (size_t)(2*q)*BATCH + row0)   = pk2(a0,b0);
            *(u64*)(g_r + (size_t)(2*q+1)*BATCH + row0) = pk2(a1,b1);
        }
    }
    STATS_TAIL();
}

// ------- pass B: h' = silu( h@(A+I) + silu(bn2(r))@lin2 + b2 ); stats(h') -------
__global__ __launch_bounds__(TPB, 3) void k_passB(const float* __restrict__ w2,
                                                  const float* __restrict__ b2, int layer){
    __shared__ __align__(16) u64 wa[512];   // A+I
    __shared__ __align__(16) u64 wl[512];   // lin2
    __shared__ u64 bsh[16];
    __shared__ float2 bn[DIMC];
    __shared__ float tile[8704];
    {
        const u64* srcA = (const u64*)(g_A + layer*DIMC*DIMC);
        const u64* srcL = (const u64*)(w2  + layer*DIMC*DIMC);
        for(int i = threadIdx.x; i < 512; i += TPB){ wa[i] = srcA[i]; wl[i] = srcL[i]; }
    }
    if(threadIdx.x < DIMC) bn[threadIdx.x] = make_float2(g_scale[threadIdx.x], g_shift[threadIdx.x]);
    if(threadIdx.x < 16){
        const float* bb = b2 + layer*DIMC;
        bsh[threadIdx.x] = pk2(bb[2*threadIdx.x], bb[2*threadIdx.x+1]);
    }
    int ch = threadIdx.x & 31, mrow = threadIdx.x >> 5;
    float ssum = 0.f, ssq = 0.f;
    __syncthreads();
#pragma unroll 1
    for(int s = 0; s < SWEEPS; ++s){
        int row0 = blockIdx.x*1024 + s*512 + 2*threadIdx.x;
        u64 accA[16], accB[16];
#pragma unroll
        for(int q = 0; q < 16; q++){ accA[q] = bsh[q]; accB[q] = bsh[q]; }
        // phase 1: silu(bn2(r)) @ lin2
#pragma unroll
        for(int k = 0; k < DIMC; k++){
            u64 rr = *(const u64*)(g_r + (size_t)k*BATCH + row0);
            float rA, rB; up2(rr, rA, rB);
            float2 p = bn[k];
            float sA = siluf(fmaf(rA, p.x, p.y));
            float sB = siluf(fmaf(rB, p.x, p.y));
            u64 spA = pk2(sA, sA), spB = pk2(sB, sB);
            GEMV_STEP(wl, k, spA, spB);
        }
        // phase 2: + h @ (A + I)
#pragma unroll
        for(int k = 0; k < DIMC; k++){
            u64 hh = *(const u64*)(g_h + (size_t)k*BATCH + row0);
            float hA, hB; up2(hh, hA, hB);
            u64 spA = pk2(hA, hA), spB = pk2(hB, hB);
            GEMV_STEP(wa, k, spA, spB);
        }
        // silu on outputs (in place)
#pragma unroll
        for(int q = 0; q < 16; q++){
            float a0,a1,b0,b1; up2(accA[q],a0,a1); up2(accB[q],b0,b1);
            accA[q] = pk2(siluf(a0), siluf(a1));
            accB[q] = pk2(siluf(b0), siluf(b1));
        }
        STATS_PHASE(accA);
        STATS_PHASE(accB);
#pragma unroll
        for(int q = 0; q < 16; q++){
            float a0,a1,b0,b1; up2(accA[q],a0,a1); up2(accB[q],b0,b1);
            *(u64*)(g_h + (size_t)(2*q)*BATCH + row0)   = pk2(a0,b0);
            *(u64*)(g_h + (size_t)(2*q+1)*BATCH + row0) = pk2(a1,b1);
        }
    }
    STATS_TAIL();
}

// ---------------- head: out = h @ head_w + head_b (coalesced via smem) ----------------
__global__ __launch_bounds__(TPB, 3) void k_head(const float* __restrict__ hw,
                                                 const float* __restrict__ hb,
                                                 float* __restrict__ out){
    __shared__ float wsh[DIMC*INDIM];
    __shared__ float bshf[INDIM];
    __shared__ float tile[512*INDIM];
    for(int i = threadIdx.x; i < DIMC*INDIM; i += TPB) wsh[i] = hw[i];
    if(threadIdx.x < INDIM) bshf[threadIdx.x] = hb[threadIdx.x];
    __syncthreads();
#pragma unroll 1
    for(int s = 0; s < SWEEPS; ++s){
        int rowbase = blockIdx.x*1024 + s*512;
        int row0 = rowbase + 2*threadIdx.x;
        float accA[INDIM], accB[INDIM];
#pragma unroll
        for(int i = 0; i < INDIM; i++){ accA[i] = bshf[i]; accB[i] = bshf[i]; }
#pragma unroll 8
        for(int c = 0; c < DIMC; c++){
            u64 hh = *(const u64*)(g_h + (size_t)c*BATCH + row0);
            float hA, hB; up2(hh, hA, hB);
#pragma unroll
            for(int i = 0; i < INDIM; i++){
                float w = wsh[c*INDIM + i];
                accA[i] = fmaf(hA, w, accA[i]);
                accB[i] = fmaf(hB, w, accB[i]);
            }
        }
        __syncthreads();
#pragma unroll
        for(int i = 0; i < INDIM; i++){
            tile[(2*threadIdx.x)*INDIM + i]   = accA[i];
            tile[(2*threadIdx.x+1)*INDIM + i] = accB[i];
        }
        __syncthreads();
        for(int k = threadIdx.x; k < 512*INDIM; k += TPB)
            out[(size_t)rowbase*INDIM + k] = tile[k];
    }
}

// ---------------- launch ----------------
extern "C" void kernel_launch(void* const* d_in, const int* in_sizes, int n_in,
                              void* d_out, int out_size) {
    (void)in_sizes; (void)n_in; (void)out_size;
    const float* x      = (const float*)d_in[0];
    const float* stem_w = (const float*)d_in[1];
    const float* stem_b = (const float*)d_in[2];
    const float* fno_wr = (const float*)d_in[3];
    const float* fno_wi = (const float*)d_in[4];
    const float* bn1_g  = (const float*)d_in[5];
    const float* bn1_b  = (const float*)d_in[6];
    const float* lin1_w = (const float*)d_in[7];
    const float* lin1_b = (const float*)d_in[8];
    const float* bn2_g  = (const float*)d_in[9];
    const float* bn2_b  = (const float*)d_in[10];
    const float* lin2_w = (const float*)d_in[11];
    const float* lin2_b = (const float*)d_in[12];
    const float* head_w = (const float*)d_in[13];
    const float* head_b = (const float*)d_in[14];
    float* out = (float*)d_out;

    k_precompute_A<<<16, 256>>>(fno_wr, fno_wi);
    k_stem<<<GRID_MAIN, TPB>>>(x, stem_w, stem_b);
    for(int l = 0; l < LAYERS; l++){
        k_fin<<<1, 1024>>>(bn1_g, bn1_b, l);          // stats of h -> bn1 affine
        k_passA<<<GRID_MAIN, TPB>>>(lin1_w, lin1_b, l);
        k_fin<<<1, 1024>>>(bn2_g, bn2_b, l);          // stats of r -> bn2 affine
        k_passB<<<GRID_MAIN, TPB>>>(lin2_w, lin2_b, l);
    }
    k_head<<<GRID_MAIN, TPB>>>(head_w, head_b, out);
}

// round 8
// speedup vs baseline: 3.1876x; 3.1876x over previous
#include <cuda_runtime.h>

#define BATCH   2097152
#define DIMC    32
#define INDIM   10
#define LAYERS  4
#define MB      17
#define EPSV    1e-5f

#define GRID_MAIN 2048
#define TPB       256
#define RPT       4                       // stem/head: 1 row/thread, 4 iters
#define STRIDE    (GRID_MAIN*TPB)
#define SWEEPS    2                       // passA/B: 2 rows/thread, 2 sweeps

typedef unsigned long long u64;

// ---------------- scratch (__device__ globals: allocation-free) ----------------
__device__ __align__(16) float g_h[(size_t)DIMC * BATCH];   // planar [c][row]
__device__ __align__(16) float g_r[(size_t)DIMC * BATCH];   // planar [c][row]
__device__ __align__(16) float g_A[LAYERS * DIMC * DIMC];   // fused Fourier A+I, [l][in][out]
__device__ float g_partials[GRID_MAIN * 64];                // per-CTA [sum[32], sumsq[32]]
__device__ float g_scale[DIMC];                             // BN affine: y = x*scale + shift
__device__ float g_shift[DIMC];

// ---------------- packed f32x2 helpers ----------------
__device__ __forceinline__ u64 pk2(float a, float b){
    u64 r; asm("mov.b64 %0,{%1,%2};" : "=l"(r) : "f"(a), "f"(b)); return r;
}
__device__ __forceinline__ void up2(u64 v, float &a, float &b){
    asm("mov.b64 {%0,%1},%2;" : "=f"(a), "=f"(b) : "l"(v));
}
__device__ __forceinline__ u64 fma2(u64 a, u64 b, u64 c){
    u64 d; asm("fma.rn.f32x2 %0,%1,%2,%3;" : "=l"(d) : "l"(a), "l"(b), "l"(c)); return d;
}
__device__ __forceinline__ float siluf(float x){
    return x * __fdividef(1.0f, 1.0f + __expf(-x));
}

// ------- Fourier operator precompute: A' = A + I. One thread per element. -------
__global__ void k_precompute_A(const float* __restrict__ wr, const float* __restrict__ wi){
    __shared__ double ct[32], st[32];
    int t = threadIdx.x;
    if(t < 32){
        double ang = 6.283185307179586476925286766559 * (double)t / 32.0;
        ct[t] = cos(ang); st[t] = sin(ang);
    }
    __syncthreads();
    int g = blockIdx.x * blockDim.x + t;               // 0..4095
    if(g >= LAYERS*DIMC*DIMC) return;
    int l = g >> 10, j = (g >> 5) & 31, d = g & 31;
    const float* WR = wr + l*MB*MB;
    const float* WI = wi + l*MB*MB;
    double v = 0.0;
    for(int k = 0; k < MB; k++){
        double re = 0.0, im = 0.0;
        for(int m = 0; m < MB; m++){
            double c = ct[(m*j)&31], s = st[(m*j)&31];   // rfft of e_j: c - i*s
            double a = (double)WR[m*MB + k], b = (double)WI[m*MB + k];
            re += c*a + s*b;
            im += c*b - s*a;
        }
        double al, be;
        if(k == 0)      { al = 1.0; be = 0.0; }
        else if(k == 16){ al = (d & 1) ? -1.0 : 1.0; be = 0.0; }
        else            { al = 2.0*ct[(k*d)&31]; be = 2.0*st[(k*d)&31]; }
        v += al*re - be*im;
    }
    v *= (1.0/32.0);
    if(j == d) v += 1.0;                                  // fold identity skip
    g_A[(l*DIMC + j)*DIMC + d] = (float)v;
}

// ---- stats via shared tile: [256 rows][35] floats, conflict-free both directions ----
// Writes one acc set (16 u64 = 32 floats) as floats, then accumulates transposed.
#define STATS_PHASE(ACC) do{                                                   \
    __syncthreads();                                                           \
    { float* trow = tile + threadIdx.x*35;                                     \
      _Pragma("unroll")                                                        \
      for(int q = 0; q < 16; q++){                                             \
          float _a,_b; up2((ACC)[q],_a,_b);                                    \
          trow[2*q] = _a; trow[2*q+1] = _b;                                    \
      } }                                                                      \
    __syncthreads();                                                           \
    _Pragma("unroll")                                                          \
    for(int j = 0; j < 32; j++){                                               \
        float v = tile[(mrow*32 + j)*35 + ch];                                 \
        ssum += v; ssq += v*v;                                                 \
    }                                                                          \
}while(0)

#define STATS_TAIL() do{                                                       \
    __syncthreads();                                                           \
    tile[mrow*64 + ch]      = ssum;                                            \
    tile[mrow*64 + 32 + ch] = ssq;                                             \
    __syncthreads();                                                           \
    if(threadIdx.x < 64){                                                      \
        float v = 0.f;                                                         \
        _Pragma("unroll")                                                      \
        for(int m = 0; m < 8; m++) v += tile[m*64 + threadIdx.x];              \
        g_partials[blockIdx.x*64 + threadIdx.x] = v;                           \
    }                                                                          \
}while(0)

// one k-step of the 2-row GEMV: acc{A,B}[16] += sp{A,B} * w[k][:]
#define GEMV_STEP(WSH, K, SPA, SPB) do{                                        \
    const ulonglong2* _w2 = (const ulonglong2*)((WSH) + (K)*16);               \
    _Pragma("unroll")                                                          \
    for(int i = 0; i < 8; i++){                                                \
        ulonglong2 ww = _w2[i];                                                \
        accA[2*i]   = fma2((SPA), ww.x, accA[2*i]);                            \
        accB[2*i]   = fma2((SPB), ww.x, accB[2*i]);                            \
        accA[2*i+1] = fma2((SPA), ww.y, accA[2*i+1]);                          \
        accB[2*i+1] = fma2((SPB), ww.y, accB[2*i+1]);                          \
    }                                                                          \
}while(0)

// ---------------- stem: h = x@stem_w + b; stats(h)  (round-6 verbatim) ----------------
__global__ __launch_bounds__(TPB) void k_stem(const float* __restrict__ x,
                                              const float* __restrict__ sw,
                                              const float* __restrict__ sb){
    __shared__ __align__(16) u64 wsh[INDIM*16];
    __shared__ u64 bsh[16];
    __shared__ float tile[8960];
    if(threadIdx.x < INDIM*16){
        int r = threadIdx.x >> 4, q = threadIdx.x & 15;
        wsh[threadIdx.x] = pk2(sw[r*DIMC + 2*q], sw[r*DIMC + 2*q + 1]);
    }
    if(threadIdx.x < 16) bsh[threadIdx.x] = pk2(sb[2*threadIdx.x], sb[2*threadIdx.x+1]);
    int ch = threadIdx.x & 31, mrow = threadIdx.x >> 5;
    float ssum = 0.f, ssq = 0.f;
    __syncthreads();
#pragma unroll 1
    for(int it = 0; it < RPT; ++it){
        int rowbase = blockIdx.x*TPB + it*STRIDE;
        int row = rowbase + threadIdx.x;
        __syncthreads();
        for(int k = threadIdx.x; k < TPB*INDIM; k += TPB)
            tile[k] = x[(size_t)rowbase*INDIM + k];
        __syncthreads();
        float xv[INDIM];
#pragma unroll
        for(int i = 0; i < INDIM; i++) xv[i] = tile[threadIdx.x*INDIM + i];
        __syncthreads();
        u64 acc[16];
#pragma unroll
        for(int q = 0; q < 16; q++) acc[q] = bsh[q];
#pragma unroll
        for(int i = 0; i < INDIM; i++){
            u64 xp = pk2(xv[i], xv[i]);
            const ulonglong2* w2 = (const ulonglong2*)(wsh + i*16);
#pragma unroll
            for(int q = 0; q < 8; q++){
                ulonglong2 ww = w2[q];
                acc[2*q]   = fma2(xp, ww.x, acc[2*q]);
                acc[2*q+1] = fma2(xp, ww.y, acc[2*q+1]);
            }
        }
        float* trow = tile + threadIdx.x*35;
#pragma unroll
        for(int q = 0; q < 16; q++){
            float a, b; up2(acc[q], a, b);
            g_h[(size_t)(2*q)*BATCH + row]   = a;
            g_h[(size_t)(2*q+1)*BATCH + row] = b;
            trow[2*q] = a; trow[2*q+1] = b;
        }
        __syncthreads();
#pragma unroll
        for(int j = 0; j < 32; j++){
            float v = tile[(mrow*32 + j)*35 + ch];
            ssum += v; ssq += v*v;
        }
    }
    STATS_TAIL();
}

// ---------------- finalize: partials -> BN scale/shift (round-6 verbatim) ----------------
__global__ void k_fin(const float* __restrict__ gamma, const float* __restrict__ beta, int layer){
    __shared__ float red[1024];
    __shared__ float tot[64];
    int t = threadIdx.x;
    int col = t & 63, part = t >> 6;
    const float* p = g_partials + (size_t)part*128*64 + col;
    float v = 0.f;
#pragma unroll 8
    for(int i = 0; i < 128; i++) v += p[(size_t)i*64];
    red[part*64 + col] = v;
    __syncthreads();
    if(t < 64){
        float s = 0.f;
#pragma unroll
        for(int q = 0; q < 16; q++) s += red[q*64 + t];
        tot[t] = s;
    }
    __syncthreads();
    if(t < DIMC){
        float mean = tot[t]      * (1.0f/(float)BATCH);
        float ex2  = tot[32 + t] * (1.0f/(float)BATCH);
        float var  = fmaxf(ex2 - mean*mean, 0.0f);
        float sc   = gamma[layer*DIMC + t] * rsqrtf(var + EPSV);
        g_scale[t] = sc;
        g_shift[t] = beta[layer*DIMC + t] - mean*sc;
    }
}

// ------- pass A: r = silu(bn1(h))@lin1 + b1; stats(r). 2 rows/thread, float2 I/O -------
__global__ __launch_bounds__(TPB, 2) void k_passA(const float* __restrict__ w1,
                                                  const float* __restrict__ b1, int layer){
    __shared__ __align__(16) u64 wsh[512];
    __shared__ u64 bsh[16];
    __shared__ float2 bn[DIMC];
    __shared__ float tile[8960];
    {
        const u64* src = (const u64*)(w1 + layer*DIMC*DIMC);
        for(int i = threadIdx.x; i < 512; i += TPB) wsh[i] = src[i];
    }
    if(threadIdx.x < DIMC) bn[threadIdx.x] = make_float2(g_scale[threadIdx.x], g_shift[threadIdx.x]);
    if(threadIdx.x < 16){
        const float* bb = b1 + layer*DIMC;
        bsh[threadIdx.x] = pk2(bb[2*threadIdx.x], bb[2*threadIdx.x+1]);
    }
    int ch = threadIdx.x & 31, mrow = threadIdx.x >> 5;
    float ssum = 0.f, ssq = 0.f;
    __syncthreads();
#pragma unroll 1
    for(int s = 0; s < SWEEPS; ++s){
        int row0 = blockIdx.x*1024 + s*512 + 2*threadIdx.x;
        u64 accA[16], accB[16];
#pragma unroll
        for(int q = 0; q < 16; q++){ accA[q] = bsh[q]; accB[q] = bsh[q]; }
#pragma unroll
        for(int k = 0; k < DIMC; k++){
            float2 hh = *(const float2*)(g_h + (size_t)k*BATCH + row0);
            float2 p = bn[k];
            float sA = siluf(fmaf(hh.x, p.x, p.y));
            float sB = siluf(fmaf(hh.y, p.x, p.y));
            u64 spA = pk2(sA, sA), spB = pk2(sB, sB);
            GEMV_STEP(wsh, k, spA, spB);
        }
        STATS_PHASE(accA);
        STATS_PHASE(accB);
#pragma unroll
        for(int q = 0; q < 16; q++){
            float a0,a1,b0,b1; up2(accA[q],a0,a1); up2(accB[q],b0,b1);
            *(float2*)(g_r + (size_t)(2*q)*BATCH + row0)   = make_float2(a0, b0);
            *(float2*)(g_r + (size_t)(2*q+1)*BATCH + row0) = make_float2(a1, b1);
        }
    }
    STATS_TAIL();
}

// ------- pass B: h' = silu( h@(A+I) + silu(bn2(r))@lin2 + b2 ); stats(h') -------
__global__ __launch_bounds__(TPB, 2) void k_passB(const float* __restrict__ w2,
                                                  const float* __restrict__ b2, int layer){
    __shared__ __align__(16) u64 wa[512];   // A+I
    __shared__ __align__(16) u64 wl[512];   // lin2
    __shared__ u64 bsh[16];
    __shared__ float2 bn[DIMC];
    __shared__ float tile[8960];
    {
        const u64* srcA = (const u64*)(g_A + layer*DIMC*DIMC);
        const u64* srcL = (const u64*)(w2  + layer*DIMC*DIMC);
        for(int i = threadIdx.x; i < 512; i += TPB){ wa[i] = srcA[i]; wl[i] = srcL[i]; }
    }
    if(threadIdx.x < DIMC) bn[threadIdx.x] = make_float2(g_scale[threadIdx.x], g_shift[threadIdx.x]);
    if(threadIdx.x < 16){
        const float* bb = b2 + layer*DIMC;
        bsh[threadIdx.x] = pk2(bb[2*threadIdx.x], bb[2*threadIdx.x+1]);
    }
    int ch = threadIdx.x & 31, mrow = threadIdx.x >> 5;
    float ssum = 0.f, ssq = 0.f;
    __syncthreads();
#pragma unroll 1
    for(int s = 0; s < SWEEPS; ++s){
        int row0 = blockIdx.x*1024 + s*512 + 2*threadIdx.x;
        u64 accA[16], accB[16];
#pragma unroll
        for(int q = 0; q < 16; q++){ accA[q] = bsh[q]; accB[q] = bsh[q]; }
        // phase 1: silu(bn2(r)) @ lin2 + b2
#pragma unroll
        for(int k = 0; k < DIMC; k++){
            float2 rr = *(const float2*)(g_r + (size_t)k*BATCH + row0);
            float2 p = bn[k];
            float sA = siluf(fmaf(rr.x, p.x, p.y));
            float sB = siluf(fmaf(rr.y, p.x, p.y));
            u64 spA = pk2(sA, sA), spB = pk2(sB, sB);
            GEMV_STEP(wl, k, spA, spB);
        }
        // phase 2: + h @ (A + I)
#pragma unroll
        for(int k = 0; k < DIMC; k++){
            float2 hh = *(const float2*)(g_h + (size_t)k*BATCH + row0);
            u64 spA = pk2(hh.x, hh.x), spB = pk2(hh.y, hh.y);
            GEMV_STEP(wa, k, spA, spB);
        }
        // silu on outputs (in place)
#pragma unroll
        for(int q = 0; q < 16; q++){
            float a0,a1,b0,b1; up2(accA[q],a0,a1); up2(accB[q],b0,b1);
            accA[q] = pk2(siluf(a0), siluf(a1));
            accB[q] = pk2(siluf(b0), siluf(b1));
        }
        STATS_PHASE(accA);
        STATS_PHASE(accB);
#pragma unroll
        for(int q = 0; q < 16; q++){
            float a0,a1,b0,b1; up2(accA[q],a0,a1); up2(accB[q],b0,b1);
            *(float2*)(g_h + (size_t)(2*q)*BATCH + row0)   = make_float2(a0, b0);
            *(float2*)(g_h + (size_t)(2*q+1)*BATCH + row0) = make_float2(a1, b1);
        }
    }
    STATS_TAIL();
}

// ---------------- head: out = h @ head_w + head_b (round-6 verbatim) ----------------
__global__ __launch_bounds__(TPB) void k_head(const float* __restrict__ hw,
                                              const float* __restrict__ hb,
                                              float* __restrict__ out){
    __shared__ float wsh[DIMC*INDIM];
    __shared__ float bshf[INDIM];
    __shared__ float tile[TPB*INDIM];
    for(int i = threadIdx.x; i < DIMC*INDIM; i += TPB) wsh[i] = hw[i];
    if(threadIdx.x < INDIM) bshf[threadIdx.x] = hb[threadIdx.x];
    __syncthreads();
#pragma unroll 1
    for(int it = 0; it < RPT; ++it){
        int rowbase = blockIdx.x*TPB + it*STRIDE;
        int row = rowbase + threadIdx.x;
        float acc[INDIM];
#pragma unroll
        for(int i = 0; i < INDIM; i++) acc[i] = bshf[i];
#pragma unroll 4
        for(int c = 0; c < DIMC; c++){
            float h = g_h[(size_t)c*BATCH + row];
#pragma unroll
            for(int i = 0; i < INDIM; i++) acc[i] = fmaf(h, wsh[c*INDIM + i], acc[i]);
        }
        __syncthreads();
#pragma unroll
        for(int i = 0; i < INDIM; i++) tile[threadIdx.x*INDIM + i] = acc[i];
        __syncthreads();
        for(int k = threadIdx.x; k < TPB*INDIM; k += TPB)
            out[(size_t)rowbase*INDIM + k] = tile[k];
    }
}

// ---------------- launch ----------------
extern "C" void kernel_launch(void* const* d_in, const int* in_sizes, int n_in,
                              void* d_out, int out_size) {
    (void)in_sizes; (void)n_in; (void)out_size;
    const float* x      = (const float*)d_in[0];
    const float* stem_w = (const float*)d_in[1];
    const float* stem_b = (const float*)d_in[2];
    const float* fno_wr = (const float*)d_in[3];
    const float* fno_wi = (const float*)d_in[4];
    const float* bn1_g  = (const float*)d_in[5];
    const float* bn1_b  = (const float*)d_in[6];
    const float* lin1_w = (const float*)d_in[7];
    const float* lin1_b = (const float*)d_in[8];
    const float* bn2_g  = (const float*)d_in[9];
    const float* bn2_b  = (const float*)d_in[10];
    const float* lin2_w = (const float*)d_in[11];
    const float* lin2_b = (const float*)d_in[12];
    const float* head_w = (const float*)d_in[13];
    const float* head_b = (const float*)d_in[14];
    float* out = (float*)d_out;

    k_precompute_A<<<16, 256>>>(fno_wr, fno_wi);
    k_stem<<<GRID_MAIN, TPB>>>(x, stem_w, stem_b);
    for(int l = 0; l < LAYERS; l++){
        k_fin<<<1, 1024>>>(bn1_g, bn1_b, l);          // stats of h -> bn1 affine
        k_passA<<<GRID_MAIN, TPB>>>(lin1_w, lin1_b, l);
        k_fin<<<1, 1024>>>(bn2_g, bn2_b, l);          // stats of r -> bn2 affine
        k_passB<<<GRID_MAIN, TPB>>>(lin2_w, lin2_b, l);
    }
    k_head<<<GRID_MAIN, TPB>>>(head_w, head_b, out);
}